// round 2
// baseline (speedup 1.0000x reference)
#include <cuda_runtime.h>
#include <math.h>

#define NEDGE 320000
#define NUN   10000
#define NVN   10000
#define EOUT  256
#define FIN   128

// ---------------- scratch (static device globals; no allocation) ------------
__device__ float    g_pu[NUN * 256];     // u_feat@Wu + bu
__device__ float    g_pv[NVN * 256];     // v_feat@Wv + bv
__device__ float    g_att_u[NUN * 256];  // u_feat@Wau + bau
__device__ float    g_att_v[NVN * 256];  // v_feat@Wav + bav
__device__ float    g_agg_u[NUN * 256];
__device__ float    g_agg_v[NVN * 256];
__device__ float    g_w_bwd[NEDGE];      // logit, then exp weight
__device__ float    g_w_fwd[NEDGE];
__device__ unsigned g_m_bwd[NUN];        // encoded-order float max
__device__ unsigned g_m_fwd[NVN];
__device__ float    g_s_bwd[NUN];
__device__ float    g_s_fwd[NVN];

// monotonic float<->uint encoding so atomicMax(unsigned) == float max
__device__ __forceinline__ unsigned enc_f(float f) {
    unsigned u = __float_as_uint(f);
    return (u & 0x80000000u) ? ~u : (u | 0x80000000u);
}
__device__ __forceinline__ float dec_f(unsigned e) {
    unsigned u = (e & 0x80000000u) ? (e & 0x7FFFFFFFu) : ~e;
    return __uint_as_float(u);
}

// ---------------- init: zero aggregates / sums / maxes ----------------------
__global__ void init_kernel() {
    int i = blockIdx.x * blockDim.x + threadIdx.x;
    if (i < NUN * 256) g_agg_u[i] = 0.f;
    if (i < NVN * 256) g_agg_v[i] = 0.f;
    if (i < NUN) { g_s_bwd[i] = 0.f; g_m_bwd[i] = 0u; }
    if (i < NVN) { g_s_fwd[i] = 0.f; g_m_fwd[i] = 0u; }
}

// ---------------- tiled fp32 GEMM, 64x64 tile, 128 threads ------------------
// MODE 0: C = A@W + bias                 (store at C[r*ldc + col_off + n])
// MODE 2: C = relu(A@W + bias)
// MODE 3: C = relu(A@W + bias + Pu[src[r]] + Pv[dst[r]])   (he epilogue)
template <int MODE>
__launch_bounds__(128)
__global__ void gemm64(const float* __restrict__ A, int K,
                       const float* __restrict__ W, int Ntot,
                       const float* __restrict__ bias,
                       float* __restrict__ C, int ldc, int col_off, int M,
                       const int* __restrict__ src, const int* __restrict__ dst,
                       const float* __restrict__ Pu, const float* __restrict__ Pv) {
    __shared__ __align__(16) float As[16][64];
    __shared__ __align__(16) float Ws[16][64];
    const int t  = threadIdx.x;
    const int ty = t >> 3;          // 0..15
    const int tx = t & 7;           // 0..7
    const int row0 = blockIdx.y * 64;
    const int n0   = blockIdx.x * 64;

    float acc[4][8];
#pragma unroll
    for (int i = 0; i < 4; i++)
#pragma unroll
        for (int j = 0; j < 8; j++) acc[i][j] = 0.f;

    for (int k0 = 0; k0 < K; k0 += 16) {
#pragma unroll
        for (int j = 0; j < 2; j++) {     // A tile: 64 rows x 16 cols (4 f4 slots/row)
            int idx = t * 2 + j;          // 0..255 float4 slots
            int r  = idx >> 2;            // row 0..63
            int c4 = idx & 3;             // f4 slot in row
            float4 v = make_float4(0.f, 0.f, 0.f, 0.f);
            int gr = row0 + r;
            if (gr < M) v = *(const float4*)&A[(size_t)gr * K + k0 + c4 * 4];
            As[c4 * 4 + 0][r] = v.x;
            As[c4 * 4 + 1][r] = v.y;
            As[c4 * 4 + 2][r] = v.z;
            As[c4 * 4 + 3][r] = v.w;
        }
#pragma unroll
        for (int j = 0; j < 2; j++) {     // W tile: 16 rows x 64 cols (16 f4 slots/row)
            int idx = t * 2 + j;          // 0..255 float4 slots
            int kr  = idx >> 4;           // row 0..15
            int c4  = idx & 15;           // f4 slot in row 0..15
            *(float4*)&Ws[kr][c4 * 4] =
                *(const float4*)&W[(size_t)(k0 + kr) * Ntot + n0 + c4 * 4];
        }
        __syncthreads();
#pragma unroll
        for (int kk = 0; kk < 16; kk++) {
            float4 a  = *(const float4*)&As[kk][ty * 4];
            float4 b0 = *(const float4*)&Ws[kk][tx * 8];
            float4 b1 = *(const float4*)&Ws[kk][tx * 8 + 4];
            float av[4] = {a.x, a.y, a.z, a.w};
            float bv[8] = {b0.x, b0.y, b0.z, b0.w, b1.x, b1.y, b1.z, b1.w};
#pragma unroll
            for (int i = 0; i < 4; i++)
#pragma unroll
                for (int j = 0; j < 8; j++) acc[i][j] = fmaf(av[i], bv[j], acc[i][j]);
        }
        __syncthreads();
    }

#pragma unroll
    for (int i = 0; i < 4; i++) {
        int r = row0 + ty * 4 + i;
        if (r >= M) continue;
        int s_ = 0, d_ = 0;
        if (MODE == 3) { s_ = src[r]; d_ = dst[r]; }
#pragma unroll
        for (int j = 0; j < 8; j++) {
            int n = n0 + tx * 8 + j;
            float v = acc[i][j] + bias[n];
            if (MODE == 3) v += Pu[s_ * 256 + n] + Pv[d_ * 256 + n];
            if (MODE == 2 || MODE == 3) v = fmaxf(v, 0.f);
            C[(size_t)r * ldc + col_off + n] = v;
        }
    }
}

// ---------------- edge attention logits + segment max -----------------------
// one warp per edge; 8 edges / 256-thread block
__global__ void edotv_kernel(const float* __restrict__ e_feat,
                             const float* __restrict__ u_feat,
                             const float* __restrict__ v_feat,
                             const int* __restrict__ src,
                             const int* __restrict__ dst) {
    int e = blockIdx.x * 8 + (threadIdx.x >> 5);
    if (e >= NEDGE) return;
    int lane = threadIdx.x & 31;
    int s = src[e], d = dst[e];
    const float* au = g_att_u + (size_t)s * 256;
    const float* av = g_att_v + (size_t)d * 256;
    const float* uv = u_feat + (size_t)s * FIN;
    const float* vv = v_feat + (size_t)d * FIN;
    const float* ev = e_feat + (size_t)e * FIN;
    float sb = 0.f, sf = 0.f;
#pragma unroll
    for (int q = 0; q < 4; q++) {
        int c = lane + q * 32;
        float ef = ev[c];
        sb += vv[c] * au[c] + ef * au[c + 128];
        sf += uv[c] * av[c] + ef * av[c + 128];
    }
#pragma unroll
    for (int o = 16; o; o >>= 1) {
        sb += __shfl_xor_sync(0xFFFFFFFFu, sb, o);
        sf += __shfl_xor_sync(0xFFFFFFFFu, sf, o);
    }
    if (lane == 0) {
        g_w_bwd[e] = sb;
        g_w_fwd[e] = sf;
        atomicMax(&g_m_bwd[s], enc_f(sb));
        atomicMax(&g_m_fwd[d], enc_f(sf));
    }
}

// ---------------- exp(logit - max) + segment sum -----------------------------
__global__ void expsum_kernel(const int* __restrict__ src, const int* __restrict__ dst) {
    int e = blockIdx.x * 256 + threadIdx.x;
    if (e >= NEDGE) return;
    int s = src[e], d = dst[e];
    float wb = expf(g_w_bwd[e] - dec_f(g_m_bwd[s]));
    float wf = expf(g_w_fwd[e] - dec_f(g_m_fwd[d]));
    g_w_bwd[e] = wb;
    g_w_fwd[e] = wf;
    atomicAdd(&g_s_bwd[s], wb);
    atomicAdd(&g_s_fwd[d], wf);
}

// ---------------- weighted scatter-sum aggregation ---------------------------
__global__ void agg_kernel(const float* __restrict__ e_feat,
                           const float* __restrict__ u_feat,
                           const float* __restrict__ v_feat,
                           const int* __restrict__ src,
                           const int* __restrict__ dst) {
    int e = blockIdx.x * 8 + (threadIdx.x >> 5);
    if (e >= NEDGE) return;
    int lane = threadIdx.x & 31;
    int s = src[e], d = dst[e];
    float cb = g_w_bwd[e] / g_s_bwd[s];
    float cf = g_w_fwd[e] / g_s_fwd[d];
    const float* ev = e_feat + (size_t)e * FIN;
    const float* vv = v_feat + (size_t)d * FIN;
    const float* uv = u_feat + (size_t)s * FIN;
    float* agu = g_agg_u + (size_t)s * 256;
    float* agv = g_agg_v + (size_t)d * 256;
#pragma unroll
    for (int q = 0; q < 4; q++) {
        int c = lane + q * 32;
        float ef = ev[c];
        atomicAdd(&agu[c], cb * vv[c]);
        atomicAdd(&agu[c + 128], cb * ef);
        atomicAdd(&agv[c], cf * uv[c]);
        atomicAdd(&agv[c + 128], cf * ef);
    }
}

// ---------------- launch ------------------------------------------------------
extern "C" void kernel_launch(void* const* d_in, const int* in_sizes, int n_in,
                              void* d_out, int out_size) {
    const float* e_feat = (const float*)d_in[0];
    const float* u_feat = (const float*)d_in[1];
    const float* v_feat = (const float*)d_in[2];
    const int*   src    = (const int*)d_in[3];
    const int*   dst    = (const int*)d_in[4];
    const float* We  = (const float*)d_in[5];  const float* be  = (const float*)d_in[6];
    const float* Wu  = (const float*)d_in[7];  const float* bu  = (const float*)d_in[8];
    const float* Wv  = (const float*)d_in[9];  const float* bv  = (const float*)d_in[10];
    const float* Wau = (const float*)d_in[11]; const float* bau = (const float*)d_in[12];
    const float* Wav = (const float*)d_in[13]; const float* bav = (const float*)d_in[14];
    const float* Wnu = (const float*)d_in[15]; const float* bnu = (const float*)d_in[16];
    const float* Wnv = (const float*)d_in[17]; const float* bnv = (const float*)d_in[18];
    const float* Vu  = (const float*)d_in[19]; const float* bVu = (const float*)d_in[20];
    const float* Vv  = (const float*)d_in[21]; const float* bVv = (const float*)d_in[22];

    float* out    = (float*)d_out;
    float* out_he = out;
    float* out_hu = out + (size_t)NEDGE * 256;
    float* out_hv = out_hu + (size_t)NUN * 256;

    float *pu, *pv, *au, *av, *aggu, *aggv;
    cudaGetSymbolAddress((void**)&pu,   g_pu);
    cudaGetSymbolAddress((void**)&pv,   g_pv);
    cudaGetSymbolAddress((void**)&au,   g_att_u);
    cudaGetSymbolAddress((void**)&av,   g_att_v);
    cudaGetSymbolAddress((void**)&aggu, g_agg_u);
    cudaGetSymbolAddress((void**)&aggv, g_agg_v);

    // init scratch
    init_kernel<<<(NUN * 256 + 255) / 256, 256>>>();

    const int MB_U = (NUN + 63) / 64;   // 157
    const int MB_V = (NVN + 63) / 64;

    // node projections (to scratch)
    gemm64<0><<<dim3(4, MB_U), 128>>>(u_feat, 128, Wu, 256, bu, pu, 256, 0, NUN,
                                      nullptr, nullptr, nullptr, nullptr);
    gemm64<0><<<dim3(4, MB_V), 128>>>(v_feat, 128, Wv, 256, bv, pv, 256, 0, NVN,
                                      nullptr, nullptr, nullptr, nullptr);
    gemm64<0><<<dim3(4, MB_U), 128>>>(u_feat, 128, Wau, 256, bau, au, 256, 0, NUN,
                                      nullptr, nullptr, nullptr, nullptr);
    gemm64<0><<<dim3(4, MB_V), 128>>>(v_feat, 128, Wav, 256, bav, av, 256, 0, NVN,
                                      nullptr, nullptr, nullptr, nullptr);
    // skip-connection halves of hu / hv (no relu)
    gemm64<0><<<dim3(2, MB_U), 128>>>(u_feat, 128, Vu, 128, bVu, out_hu, 256, 0, NUN,
                                      nullptr, nullptr, nullptr, nullptr);
    gemm64<0><<<dim3(2, MB_V), 128>>>(v_feat, 128, Vv, 128, bVv, out_hv, 256, 0, NVN,
                                      nullptr, nullptr, nullptr, nullptr);

    // he = relu(e@We + be + pu[src] + pv[dst])  (the big GEMM, fused epilogue)
    gemm64<3><<<dim3(4, NEDGE / 64), 128>>>(e_feat, 128, We, 256, be, out_he, 256, 0,
                                            NEDGE, src, dst, pu, pv);

    // attention logits + segment max
    edotv_kernel<<<(NEDGE + 7) / 8, 256>>>(e_feat, u_feat, v_feat, src, dst);
    // exp + segment sum
    expsum_kernel<<<(NEDGE + 255) / 256, 256>>>(src, dst);
    // weighted aggregation
    agg_kernel<<<(NEDGE + 7) / 8, 256>>>(e_feat, u_feat, v_feat, src, dst);

    // node output heads: relu(agg @ Wn + bn) into second half of hu / hv
    gemm64<2><<<dim3(2, MB_U), 128>>>(aggu, 256, Wnu, 128, bnu, out_hu, 256, 128, NUN,
                                      nullptr, nullptr, nullptr, nullptr);
    gemm64<2><<<dim3(2, MB_V), 128>>>(aggv, 256, Wnv, 128, bnv, out_hv, 256, 128, NVN,
                                      nullptr, nullptr, nullptr, nullptr);
}

// round 3
// speedup vs baseline: 1.9047x; 1.9047x over previous
#include <cuda_runtime.h>
#include <math.h>
#include <stdint.h>

#define NEDGE 320000
#define NUN   10000
#define NVN   10000
#define FIN   128

// ---------------- scratch (static device globals; no allocation) ------------
__device__ float    g_pu[NUN * 256];     // u_feat@Wu + bu
__device__ float    g_pv[NVN * 256];     // v_feat@Wv + bv
__device__ float    g_att_u[NUN * 256];  // u_feat@Wau + bau   (fp32 path)
__device__ float    g_att_v[NVN * 256];  // v_feat@Wav + bav   (fp32 path)
__device__ float    g_agg_u[NUN * 256];
__device__ float    g_agg_v[NVN * 256];
__device__ float    g_w_bwd[NEDGE];      // logit, then exp weight
__device__ float    g_w_fwd[NEDGE];
__device__ unsigned g_m_bwd[NUN];        // encoded-order float max
__device__ unsigned g_m_fwd[NVN];
__device__ float    g_s_bwd[NUN];
__device__ float    g_s_fwd[NVN];

// monotonic float<->uint encoding so atomicMax(unsigned) == float max
__device__ __forceinline__ unsigned enc_f(float f) {
    unsigned u = __float_as_uint(f);
    return (u & 0x80000000u) ? ~u : (u | 0x80000000u);
}
__device__ __forceinline__ float dec_f(unsigned e) {
    unsigned u = (e & 0x80000000u) ? (e & 0x7FFFFFFFu) : ~e;
    return __uint_as_float(u);
}

__device__ __forceinline__ float f2tf32(float f) {
    uint32_t r;
    asm("cvt.rna.tf32.f32 %0, %1;" : "=r"(r) : "f"(f));
    return __uint_as_float(r);
}

__device__ __forceinline__ void mma_tf32(float* d, const uint32_t* a,
                                         uint32_t b0, uint32_t b1) {
    asm volatile(
        "mma.sync.aligned.m16n8k8.row.col.f32.tf32.tf32.f32 "
        "{%0,%1,%2,%3}, {%4,%5,%6,%7}, {%8,%9}, {%0,%1,%2,%3};"
        : "+f"(d[0]), "+f"(d[1]), "+f"(d[2]), "+f"(d[3])
        : "r"(a[0]), "r"(a[1]), "r"(a[2]), "r"(a[3]), "r"(b0), "r"(b1));
}

// ---------------- init: zero aggregates / sums / maxes ----------------------
__global__ void init_kernel() {
    int i = blockIdx.x * blockDim.x + threadIdx.x;
    if (i < NUN * 256) g_agg_u[i] = 0.f;
    if (i < NVN * 256) g_agg_v[i] = 0.f;
    if (i < NUN) { g_s_bwd[i] = 0.f; g_m_bwd[i] = 0u; }
    if (i < NVN) { g_s_fwd[i] = 0.f; g_m_fwd[i] = 0u; }
}

// =====================  tf32 tensor-core GEMM  ===============================
// C[M x BN] = op(A[M x KTOT] @ W[KTOT x BN] + bias)
// BM = 64 rows per CTA, 128 threads (4 warps), warp tile 64 x (BN/4),
// mma.m16n8k8.tf32, K chunks of 32 in shared memory.
// MODE 0: plain    MODE 2: relu    MODE 3: relu(.. + Pu[src[r]] + Pv[dst[r]])
template <int BN, int KTOT, int MODE>
__launch_bounds__(128)
__global__ void tf32gemm(const float* __restrict__ A,
                         const float* __restrict__ W,
                         const float* __restrict__ bias,
                         float* __restrict__ C, int ldc, int col_off, int M,
                         const int* __restrict__ src, const int* __restrict__ dst,
                         const float* __restrict__ Pu, const float* __restrict__ Pv) {
    constexpr int KC = 32;
    constexpr int WN = BN / 4;            // 64 or 32 cols per warp
    constexpr int NT = WN / 8;            // n-tiles per warp (8 or 4)
    constexpr int ASTR = KC + 4;          // 36 ≡ 4 (mod 32): conflict-free A frags
    constexpr int BSTR = BN + 8;          // ≡ 8 (mod 32): conflict-free B frags
    __shared__ float As[64 * ASTR];
    __shared__ float Bs[KC * BSTR];

    const int t    = threadIdx.x;
    const int warp = t >> 5;
    const int lane = t & 31;
    const int qr   = lane >> 2;           // 0..7
    const int qc   = lane & 3;            // 0..3
    const int row0 = blockIdx.x * 64;

    float acc[4][NT][4];
#pragma unroll
    for (int i = 0; i < 4; i++)
#pragma unroll
        for (int j = 0; j < NT; j++)
#pragma unroll
            for (int q = 0; q < 4; q++) acc[i][j][q] = 0.f;

    for (int k0 = 0; k0 < KTOT; k0 += KC) {
        // ---- A chunk: 64 x 32 floats = 512 float4 slots, 4 per thread ----
#pragma unroll
        for (int p = 0; p < 4; p++) {
            int slot = t + p * 128;
            int r = slot >> 3;            // 0..63
            int c = slot & 7;             // f4 slot in the 32-wide chunk
            float4 v = make_float4(0.f, 0.f, 0.f, 0.f);
            if (row0 + r < M)
                v = *(const float4*)&A[(size_t)(row0 + r) * KTOT + k0 + c * 4];
            float* s = &As[r * ASTR + c * 4];
            s[0] = f2tf32(v.x); s[1] = f2tf32(v.y);
            s[2] = f2tf32(v.z); s[3] = f2tf32(v.w);
        }
        // ---- B chunk: 32 x BN floats ----
#pragma unroll
        for (int p = 0; p < KC * BN / 512; p++) {
            int slot = t + p * 128;
            int kr = slot / (BN / 4);
            int c  = slot % (BN / 4);
            float4 v = *(const float4*)&W[(size_t)(k0 + kr) * BN + c * 4];
            float* s = &Bs[kr * BSTR + c * 4];
            s[0] = f2tf32(v.x); s[1] = f2tf32(v.y);
            s[2] = f2tf32(v.z); s[3] = f2tf32(v.w);
        }
        __syncthreads();

#pragma unroll
        for (int kk = 0; kk < KC; kk += 8) {
            uint32_t a[4][4];
#pragma unroll
            for (int i = 0; i < 4; i++) {
                const float* base = &As[(16 * i + qr) * ASTR + kk + qc];
                a[i][0] = __float_as_uint(base[0]);
                a[i][1] = __float_as_uint(base[8 * ASTR]);
                a[i][2] = __float_as_uint(base[4]);
                a[i][3] = __float_as_uint(base[8 * ASTR + 4]);
            }
#pragma unroll
            for (int j = 0; j < NT; j++) {
                int n = warp * WN + j * 8 + qr;
                uint32_t b0 = __float_as_uint(Bs[(kk + qc) * BSTR + n]);
                uint32_t b1 = __float_as_uint(Bs[(kk + 4 + qc) * BSTR + n]);
#pragma unroll
                for (int i = 0; i < 4; i++) mma_tf32(acc[i][j], a[i], b0, b1);
            }
        }
        __syncthreads();
    }

    // ---- epilogue ----
#pragma unroll
    for (int i = 0; i < 4; i++) {
#pragma unroll
        for (int h = 0; h < 2; h++) {
            int lr = 16 * i + qr + 8 * h;
            int gr = row0 + lr;
            if (gr >= M) continue;
            int s_ = 0, d_ = 0;
            if (MODE == 3) { s_ = src[gr]; d_ = dst[gr]; }
#pragma unroll
            for (int j = 0; j < NT; j++) {
                int col = warp * WN + j * 8 + 2 * qc;
                float x0 = acc[i][j][2 * h]     + bias[col];
                float x1 = acc[i][j][2 * h + 1] + bias[col + 1];
                if (MODE == 3) {
                    const float* pu = &g_pu[0] + (size_t)s_ * 256 + col;
                    const float* pv = &g_pv[0] + (size_t)d_ * 256 + col;
                    (void)Pu; (void)Pv;
                    x0 += pu[0] + pv[0];
                    x1 += pu[1] + pv[1];
                }
                if (MODE >= 2) { x0 = fmaxf(x0, 0.f); x1 = fmaxf(x1, 0.f); }
                float2* o = (float2*)&C[(size_t)gr * ldc + col_off + col];
                *o = make_float2(x0, x1);
            }
        }
    }
}

// ---------------- fp32 SIMT GEMM (kept for attention projections) -----------
__launch_bounds__(128)
__global__ void gemm64_f32(const float* __restrict__ A, int K,
                           const float* __restrict__ W, int Ntot,
                           const float* __restrict__ bias,
                           float* __restrict__ C, int ldc, int M) {
    __shared__ __align__(16) float As[16][64];
    __shared__ __align__(16) float Ws[16][64];
    const int t  = threadIdx.x;
    const int ty = t >> 3;
    const int tx = t & 7;
    const int row0 = blockIdx.y * 64;
    const int n0   = blockIdx.x * 64;

    float acc[4][8];
#pragma unroll
    for (int i = 0; i < 4; i++)
#pragma unroll
        for (int j = 0; j < 8; j++) acc[i][j] = 0.f;

    for (int k0 = 0; k0 < K; k0 += 16) {
#pragma unroll
        for (int j = 0; j < 2; j++) {
            int idx = t * 2 + j;
            int r  = idx >> 2;
            int c4 = idx & 3;
            float4 v = make_float4(0.f, 0.f, 0.f, 0.f);
            int gr = row0 + r;
            if (gr < M) v = *(const float4*)&A[(size_t)gr * K + k0 + c4 * 4];
            As[c4 * 4 + 0][r] = v.x;
            As[c4 * 4 + 1][r] = v.y;
            As[c4 * 4 + 2][r] = v.z;
            As[c4 * 4 + 3][r] = v.w;
        }
#pragma unroll
        for (int j = 0; j < 2; j++) {
            int idx = t * 2 + j;
            int kr  = idx >> 4;
            int c4  = idx & 15;
            *(float4*)&Ws[kr][c4 * 4] =
                *(const float4*)&W[(size_t)(k0 + kr) * Ntot + n0 + c4 * 4];
        }
        __syncthreads();
#pragma unroll
        for (int kk = 0; kk < 16; kk++) {
            float4 a  = *(const float4*)&As[kk][ty * 4];
            float4 b0 = *(const float4*)&Ws[kk][tx * 8];
            float4 b1 = *(const float4*)&Ws[kk][tx * 8 + 4];
            float av[4] = {a.x, a.y, a.z, a.w};
            float bv[8] = {b0.x, b0.y, b0.z, b0.w, b1.x, b1.y, b1.z, b1.w};
#pragma unroll
            for (int i = 0; i < 4; i++)
#pragma unroll
                for (int j = 0; j < 8; j++) acc[i][j] = fmaf(av[i], bv[j], acc[i][j]);
        }
        __syncthreads();
    }

#pragma unroll
    for (int i = 0; i < 4; i++) {
        int r = row0 + ty * 4 + i;
        if (r >= M) continue;
#pragma unroll
        for (int j = 0; j < 8; j++) {
            int n = n0 + tx * 8 + j;
            C[(size_t)r * ldc + n] = acc[i][j] + bias[n];
        }
    }
}

// ---------------- edge attention logits + segment max -----------------------
__global__ void edotv_kernel(const float* __restrict__ e_feat,
                             const float* __restrict__ u_feat,
                             const float* __restrict__ v_feat,
                             const int* __restrict__ src,
                             const int* __restrict__ dst) {
    int e = blockIdx.x * 8 + (threadIdx.x >> 5);
    if (e >= NEDGE) return;
    int lane = threadIdx.x & 31;
    int s = src[e], d = dst[e];
    const float* au = g_att_u + (size_t)s * 256;
    const float* av = g_att_v + (size_t)d * 256;
    const float* uv = u_feat + (size_t)s * FIN;
    const float* vv = v_feat + (size_t)d * FIN;
    const float* ev = e_feat + (size_t)e * FIN;
    float sb = 0.f, sf = 0.f;
#pragma unroll
    for (int q = 0; q < 4; q++) {
        int c = lane + q * 32;
        float ef = ev[c];
        sb += vv[c] * au[c] + ef * au[c + 128];
        sf += uv[c] * av[c] + ef * av[c + 128];
    }
#pragma unroll
    for (int o = 16; o; o >>= 1) {
        sb += __shfl_xor_sync(0xFFFFFFFFu, sb, o);
        sf += __shfl_xor_sync(0xFFFFFFFFu, sf, o);
    }
    if (lane == 0) {
        g_w_bwd[e] = sb;
        g_w_fwd[e] = sf;
        atomicMax(&g_m_bwd[s], enc_f(sb));
        atomicMax(&g_m_fwd[d], enc_f(sf));
    }
}

// ---------------- exp(logit - max) + segment sum -----------------------------
__global__ void expsum_kernel(const int* __restrict__ src, const int* __restrict__ dst) {
    int e = blockIdx.x * 256 + threadIdx.x;
    if (e >= NEDGE) return;
    int s = src[e], d = dst[e];
    float wb = expf(g_w_bwd[e] - dec_f(g_m_bwd[s]));
    float wf = expf(g_w_fwd[e] - dec_f(g_m_fwd[d]));
    g_w_bwd[e] = wb;
    g_w_fwd[e] = wf;
    atomicAdd(&g_s_bwd[s], wb);
    atomicAdd(&g_s_fwd[d], wf);
}

// ---------------- weighted scatter-sum aggregation ---------------------------
__global__ void agg_kernel(const float* __restrict__ e_feat,
                           const float* __restrict__ u_feat,
                           const float* __restrict__ v_feat,
                           const int* __restrict__ src,
                           const int* __restrict__ dst) {
    int e = blockIdx.x * 8 + (threadIdx.x >> 5);
    if (e >= NEDGE) return;
    int lane = threadIdx.x & 31;
    int s = src[e], d = dst[e];
    float cb = g_w_bwd[e] / g_s_bwd[s];
    float cf = g_w_fwd[e] / g_s_fwd[d];
    const float* ev = e_feat + (size_t)e * FIN;
    const float* vv = v_feat + (size_t)d * FIN;
    const float* uv = u_feat + (size_t)s * FIN;
    float* agu = g_agg_u + (size_t)s * 256;
    float* agv = g_agg_v + (size_t)d * 256;
#pragma unroll
    for (int q = 0; q < 4; q++) {
        int c = lane + q * 32;
        float ef = ev[c];
        atomicAdd(&agu[c], cb * vv[c]);
        atomicAdd(&agu[c + 128], cb * ef);
        atomicAdd(&agv[c], cf * uv[c]);
        atomicAdd(&agv[c + 128], cf * ef);
    }
}

// ---------------- launch ------------------------------------------------------
extern "C" void kernel_launch(void* const* d_in, const int* in_sizes, int n_in,
                              void* d_out, int out_size) {
    const float* e_feat = (const float*)d_in[0];
    const float* u_feat = (const float*)d_in[1];
    const float* v_feat = (const float*)d_in[2];
    const int*   src    = (const int*)d_in[3];
    const int*   dst    = (const int*)d_in[4];
    const float* We  = (const float*)d_in[5];  const float* be  = (const float*)d_in[6];
    const float* Wu  = (const float*)d_in[7];  const float* bu  = (const float*)d_in[8];
    const float* Wv  = (const float*)d_in[9];  const float* bv  = (const float*)d_in[10];
    const float* Wau = (const float*)d_in[11]; const float* bau = (const float*)d_in[12];
    const float* Wav = (const float*)d_in[13]; const float* bav = (const float*)d_in[14];
    const float* Wnu = (const float*)d_in[15]; const float* bnu = (const float*)d_in[16];
    const float* Wnv = (const float*)d_in[17]; const float* bnv = (const float*)d_in[18];
    const float* Vu  = (const float*)d_in[19]; const float* bVu = (const float*)d_in[20];
    const float* Vv  = (const float*)d_in[21]; const float* bVv = (const float*)d_in[22];

    float* out    = (float*)d_out;
    float* out_he = out;
    float* out_hu = out + (size_t)NEDGE * 256;
    float* out_hv = out_hu + (size_t)NUN * 256;

    float *pu, *pv, *au, *av, *aggu, *aggv;
    cudaGetSymbolAddress((void**)&pu,   g_pu);
    cudaGetSymbolAddress((void**)&pv,   g_pv);
    cudaGetSymbolAddress((void**)&au,   g_att_u);
    cudaGetSymbolAddress((void**)&av,   g_att_v);
    cudaGetSymbolAddress((void**)&aggu, g_agg_u);
    cudaGetSymbolAddress((void**)&aggv, g_agg_v);

    init_kernel<<<(NUN * 256 + 255) / 256, 256>>>();

    const int MB = (NUN + 63) / 64;   // 157 row-blocks for node tables

    // node projections feeding he (tf32)
    tf32gemm<256, 128, 0><<<MB, 128>>>(u_feat, Wu, bu, pu, 256, 0, NUN,
                                       nullptr, nullptr, nullptr, nullptr);
    tf32gemm<256, 128, 0><<<MB, 128>>>(v_feat, Wv, bv, pv, 256, 0, NVN,
                                       nullptr, nullptr, nullptr, nullptr);
    // attention projections (fp32 — softmax amplifies logit error)
    gemm64_f32<<<dim3(4, MB), 128>>>(u_feat, 128, Wau, 256, bau, au, 256, NUN);
    gemm64_f32<<<dim3(4, MB), 128>>>(v_feat, 128, Wav, 256, bav, av, 256, NVN);
    // skip-connection halves of hu / hv (tf32)
    tf32gemm<128, 128, 0><<<MB, 128>>>(u_feat, Vu, bVu, out_hu, 256, 0, NUN,
                                       nullptr, nullptr, nullptr, nullptr);
    tf32gemm<128, 128, 0><<<MB, 128>>>(v_feat, Vv, bVv, out_hv, 256, 0, NVN,
                                       nullptr, nullptr, nullptr, nullptr);

    // he = relu(e@We + be + pu[src] + pv[dst])  — the big tensor-core GEMM
    tf32gemm<256, 128, 3><<<NEDGE / 64, 128>>>(e_feat, We, be, out_he, 256, 0,
                                               NEDGE, src, dst, pu, pv);

    // attention softmax + aggregation
    edotv_kernel<<<(NEDGE + 7) / 8, 256>>>(e_feat, u_feat, v_feat, src, dst);
    expsum_kernel<<<(NEDGE + 255) / 256, 256>>>(src, dst);
    agg_kernel<<<(NEDGE + 7) / 8, 256>>>(e_feat, u_feat, v_feat, src, dst);

    // node output heads: relu(agg @ Wn + bn) into second half of hu / hv (tf32)
    tf32gemm<128, 256, 2><<<MB, 128>>>(aggu, Wnu, bnu, out_hu, 256, 128, NUN,
                                       nullptr, nullptr, nullptr, nullptr);
    tf32gemm<128, 256, 2><<<MB, 128>>>(aggv, Wnv, bnv, out_hv, 256, 128, NVN,
                                       nullptr, nullptr, nullptr, nullptr);
}